// round 1
// baseline (speedup 1.0000x reference)
#include <cuda_runtime.h>

// DeformationPerturbationLayer: the reference's dense [B,N,N] tent-weight
// einsum is mathematically exact bilinear sampling (zero-padded) of the image
// at src = pixel + w[b] * bulge_displacement(pixel).
//
// image: [C=3, H=64, W=64] fp32
// w:     [B=8, 1] fp32
// out:   [B=8, C=3, H=64, W=64] fp32

#define B_ 8
#define C_ 3
#define H_ 64
#define W_ 64
#define NPIX (H_ * W_)

__global__ __launch_bounds__(256, 8)
void deform_kernel(const float* __restrict__ w,
                   const float* __restrict__ img,
                   float* __restrict__ out)
{
    int idx = blockIdx.x * blockDim.x + threadIdx.x;   // 0 .. B_*NPIX-1
    if (idx >= B_ * NPIX) return;

    int b   = idx >> 12;          // / 4096
    int pix = idx & (NPIX - 1);   // % 4096
    int y   = pix >> 6;
    int x   = pix & 63;

    float wb = w[b];

    // localized bulge displacement
    const float cx = (W_ - 1) * 0.5f;   // 31.5
    const float cy = (H_ - 1) * 0.5f;
    float dxc = cx - (float)x;          // -(x - cx)
    float dyc = cy - (float)y;
    const float inv_two_sigma2 = 1.0f / (2.0f * 16.0f * 16.0f);  // sigma = 16
    float g = expf(-(dxc * dxc + dyc * dyc) * inv_two_sigma2);

    float sx = (float)x + wb * dxc * g;
    float sy = (float)y + wb * dyc * g;

    // bilinear taps; tent weights are zero for out-of-range grid columns/rows
    float fx0 = floorf(sx);
    float fy0 = floorf(sy);
    int x0 = (int)fx0, x1 = x0 + 1;
    int y0 = (int)fy0, y1 = y0 + 1;
    float tx = sx - fx0;           // weight for x1
    float ty = sy - fy0;

    float wx0 = 1.0f - tx, wx1 = tx;
    float wy0 = 1.0f - ty, wy1 = ty;

    bool vx0 = (x0 >= 0) && (x0 < W_);
    bool vx1 = (x1 >= 0) && (x1 < W_);
    bool vy0 = (y0 >= 0) && (y0 < H_);
    bool vy1 = (y1 >= 0) && (y1 < H_);

    if (!vx0) wx0 = 0.0f;
    if (!vx1) wx1 = 0.0f;
    if (!vy0) wy0 = 0.0f;
    if (!vy1) wy1 = 0.0f;

    // clamp indices so loads stay in-bounds (weight already zeroed)
    int cx0 = vx0 ? x0 : 0;
    int cx1 = vx1 ? x1 : 0;
    int cy0 = vy0 ? y0 : 0;
    int cy1 = vy1 ? y1 : 0;

    float w00 = wy0 * wx0;
    float w01 = wy0 * wx1;
    float w10 = wy1 * wx0;
    float w11 = wy1 * wx1;

    int i00 = cy0 * W_ + cx0;
    int i01 = cy0 * W_ + cx1;
    int i10 = cy1 * W_ + cx0;
    int i11 = cy1 * W_ + cx1;

    float* ob = out + (size_t)b * (C_ * NPIX) + pix;

#pragma unroll
    for (int c = 0; c < C_; ++c) {
        const float* ic = img + c * NPIX;
        float v = w00 * __ldg(ic + i00)
                + w01 * __ldg(ic + i01)
                + w10 * __ldg(ic + i10)
                + w11 * __ldg(ic + i11);
        ob[c * NPIX] = v;
    }
}

extern "C" void kernel_launch(void* const* d_in, const int* in_sizes, int n_in,
                              void* d_out, int out_size)
{
    const float* w   = (const float*)d_in[0];   // [8,1]
    const float* img = (const float*)d_in[1];   // [3,64,64]
    float* out = (float*)d_out;                 // [8,3,64,64]

    const int total = B_ * NPIX;                // 32768 threads
    deform_kernel<<<(total + 255) / 256, 256>>>(w, img, out);
}